// round 16
// baseline (speedup 1.0000x reference)
#include <cuda_runtime.h>
#include <math.h>

#define NPOS 5000
#define NN 500

__device__ float g_q[16*64*5000];
__device__ float g_k[16*64*5000];
__device__ float g_v[16*64*5000];
__device__ float g_resid[16*32*5000];
__device__ float g_xt[160*500*32];
__device__ float g_att[160*500*500];
__device__ float g_z1[160*500*32];
__device__ float g_z2[160*500*32];
__device__ float g_z3[160*500*32];
__device__ float g_z4[160*500*32];
__device__ float g_g[160*500*32];
__device__ float g_g6[16*32*500*6];
__device__ float g_lp[16*36];
__device__ float g_Tc[16*36];
__device__ float g_wqT[96*64];
__device__ float g_wkT[96*64];
__device__ float g_wvT[32*64];
__device__ float g_qb2[640];
__device__ float g_kb2[640];
__device__ float g_vb2[640];
__device__ float g_Wc[32*64];
__device__ float g_bc[32];
__device__ float g_part[16384];
__device__ float g_stats[64];

__global__ void k_wprep(const float* wq, const float* wk, const float* linv,
                        const float* te1, const float* te1b,
                        const float* qb, const float* kb, const float* vb,
                        const float* te2, const float* lino, const float* lino_b,
                        const float* te2_b) {
    int idx = blockIdx.x * 256 + threadIdx.x;
    if (idx < 6144) {
        int kk = idx >> 6, o = idx & 63, c = kk / 3, r = kk - c * 3;
        float s = 0.f;
        for (int i = 0; i < 64; i++) s += wq[(o * 64 + i) * 3 + r] * te1[i * 32 + c];
        g_wqT[idx] = s; return;
    }
    idx -= 6144;
    if (idx < 6144) {
        int kk = idx >> 6, o = idx & 63, c = kk / 3, r = kk - c * 3;
        float s = 0.f;
        for (int i = 0; i < 64; i++) s += wk[(o * 64 + i) * 3 + r] * te1[i * 32 + c];
        g_wkT[idx] = s; return;
    }
    idx -= 6144;
    if (idx < 2048) {
        int c = idx >> 6, o = idx & 63;
        float s = 0.f;
        for (int i = 0; i < 64; i++) s += linv[o * 64 + i] * te1[i * 32 + c];
        g_wvT[idx] = s; return;
    }
    idx -= 2048;
    if (idx < 640) {
        int o = idx / 10, t = idx - o * 10;
        float s = qb[o];
        for (int r = 0; r < 3; r++) {
            int tt = t + r - 1;
            if (tt >= 0 && tt < 10)
                for (int i = 0; i < 64; i++) s += wq[(o * 64 + i) * 3 + r] * te1b[i];
        }
        g_qb2[idx] = s; return;
    }
    idx -= 640;
    if (idx < 640) {
        int o = idx / 10, t = idx - o * 10;
        float s = kb[o];
        for (int r = 0; r < 3; r++) {
            int tt = t + r - 1;
            if (tt >= 0 && tt < 10)
                for (int i = 0; i < 64; i++) s += wk[(o * 64 + i) * 3 + r] * te1b[i];
        }
        g_kb2[idx] = s; return;
    }
    idx -= 640;
    if (idx < 640) {
        int o = idx / 10;
        float s = vb[o];
        for (int i = 0; i < 64; i++) s += linv[o * 64 + i] * te1b[i];
        g_vb2[idx] = s; return;
    }
    idx -= 640;
    if (idx < 2048) {
        int o = idx >> 6, m = idx & 63;
        float s = 0.f;
        for (int j = 0; j < 64; j++) s += te2[o * 64 + j] * lino[j * 64 + m];
        g_Wc[idx] = s; return;
    }
    idx -= 2048;
    if (idx < 32) {
        float s = te2_b[idx];
        for (int j = 0; j < 64; j++) s += te2[idx * 64 + j] * lino_b[j];
        g_bc[idx] = s;
    }
}

__global__ void k_conv1(const float* x, const float* w1, const float* b1) {
    __shared__ float w1s[1024], b1s[32];
    int tid = threadIdx.x;
    for (int i = tid; i < 1024; i += 256) w1s[i] = w1[i];
    if (tid < 32) b1s[tid] = b1[tid];
    __syncthreads();
    int b = blockIdx.x, pos = blockIdx.y * 256 + tid;
    if (pos >= NPOS) return;
    float xv[32];
#pragma unroll
    for (int c = 0; c < 32; c++) xv[c] = x[(b * 32 + c) * NPOS + pos];
    for (int o = 0; o < 32; o++) {
        float a = b1s[o];
#pragma unroll
        for (int c = 0; c < 32; c++) a += w1s[o * 32 + c] * xv[c];
        g_resid[(b * 32 + o) * NPOS + pos] = a;
    }
}

extern __shared__ float dynsm[];
__device__ __forceinline__ void qkv_gemm(const float* hsh, const float* ws, int nk,
                                          const float* bias, float* out, int b,
                                          int pos0, int o0, int p0, int stride) {
    float4 a0 = {0,0,0,0}, a1 = a0, a2 = a0, a3 = a0;
    for (int kk = 0; kk < nk; kk++) {
        float4 w = *(const float4*)&ws[kk * 64 + o0];
        float4 xx = *(const float4*)&hsh[kk * stride * 64 + p0];
        a0.x += w.x*xx.x; a0.y += w.x*xx.y; a0.z += w.x*xx.z; a0.w += w.x*xx.w;
        a1.x += w.y*xx.x; a1.y += w.y*xx.y; a1.z += w.y*xx.z; a1.w += w.y*xx.w;
        a2.x += w.z*xx.x; a2.y += w.z*xx.y; a2.z += w.z*xx.z; a2.w += w.z*xx.w;
        a3.x += w.w*xx.x; a3.y += w.w*xx.y; a3.z += w.w*xx.z; a3.w += w.w*xx.w;
    }
    int pos = pos0 + p0;
    if (pos < NPOS) {
        int t0 = pos % 10;
        int t1 = (t0 + 1) % 10, t2 = (t0 + 2) % 10, t3 = (t0 + 3) % 10;
        int base = (b * 64 + o0) * NPOS + pos;
        float acc[4][4] = {{a0.x,a0.y,a0.z,a0.w},{a1.x,a1.y,a1.z,a1.w},
                           {a2.x,a2.y,a2.z,a2.w},{a3.x,a3.y,a3.z,a3.w}};
#pragma unroll
        for (int r = 0; r < 4; r++) {
            const float* brow = &bias[(o0 + r) * 10];
            *(float4*)&out[base + r * NPOS] = make_float4(
                acc[r][0] + brow[t0], acc[r][1] + brow[t1],
                acc[r][2] + brow[t2], acc[r][3] + brow[t3]);
        }
    }
}

__global__ void __launch_bounds__(256) k_qkv(const float* x) {
    float* hsh = dynsm;
    float* ws  = dynsm + 6144;
    int b = blockIdx.x, pos0 = blockIdx.y * 64, tid = threadIdx.x;
    for (int idx = tid; idx < 6144; idx += 256) {
        int kk = idx >> 6, pl = idx & 63, c = kk / 3, r = kk - c * 3;
        int pos = pos0 + pl; float v = 0.f;
        if (pos < NPOS) {
            int t = pos % 10, tt = t + r - 1;
            if (tt >= 0 && tt < 10) v = x[(b * 32 + c) * NPOS + pos + r - 1];
        }
        hsh[idx] = v;
    }
    int o0 = (tid >> 4) * 4, p0 = (tid & 15) * 4;
    for (int idx = tid; idx < 6144; idx += 256) ws[idx] = g_wqT[idx];
    __syncthreads();
    qkv_gemm(hsh, ws, 96, g_qb2, g_q, b, pos0, o0, p0, 1);
    __syncthreads();
    for (int idx = tid; idx < 6144; idx += 256) ws[idx] = g_wkT[idx];
    __syncthreads();
    qkv_gemm(hsh, ws, 96, g_kb2, g_k, b, pos0, o0, p0, 1);
    __syncthreads();
    for (int idx = tid; idx < 2048; idx += 256) ws[idx] = g_wvT[idx];
    __syncthreads();
    qkv_gemm(hsh + 64, ws, 32, g_vb2, g_v, b, pos0, o0, p0, 3);
}

__global__ void __launch_bounds__(256) k_attn() {
    float* qs = dynsm;
    float* ks = dynsm + 2560;
    float* vs = dynsm + 5120;
    float* os = dynsm + 7680;
    float* wcs = dynsm + 10240;
    float* bcs = dynsm + 12416;
    int n0 = blockIdx.x * 4, b = blockIdx.y, tid = threadIdx.x;
    for (int idx = tid; idx < 2560; idx += 256) {
        int n_l = idx / 640, rem = idx - n_l * 640;
        int ch = rem / 10, t = rem - ch * 10;
        int gi = b * 64 * NPOS + ch * NPOS + (n0 + n_l) * 10 + t;
        qs[idx] = g_q[gi]; ks[idx] = g_k[gi]; vs[idx] = g_v[gi];
    }
    for (int idx = tid; idx < 2048; idx += 256) {
        int c = idx >> 6, m = idx & 63;
        wcs[c * 68 + m] = g_Wc[idx];
    }
    if (tid < 32) bcs[tid] = g_bc[tid];
    __syncthreads();
    for (int u = tid; u < 320; u += 256) {
        int n_l = u / 80, r = u - n_l * 80;
        int hh = r / 10, t = r - hh * 10;
        int qb = n_l * 640 + hh * 80;
        float qv[8], sc[10];
#pragma unroll
        for (int d = 0; d < 8; d++) qv[d] = qs[qb + d * 10 + t];
#pragma unroll
        for (int s = 0; s < 10; s++) {
            float a = 0.f;
#pragma unroll
            for (int d = 0; d < 8; d++) a += qv[d] * ks[qb + d * 10 + s];
            sc[s] = a * 0.35355339059327373f;
        }
        float mx = sc[0];
#pragma unroll
        for (int s = 1; s < 10; s++) mx = fmaxf(mx, sc[s]);
        float sum = 0.f;
#pragma unroll
        for (int s = 0; s < 10; s++) { sc[s] = expf(sc[s] - mx); sum += sc[s]; }
        float inv = 1.f / sum;
#pragma unroll
        for (int d = 0; d < 8; d++) {
            float a = 0.f;
#pragma unroll
            for (int s = 0; s < 10; s++) a += sc[s] * vs[qb + d * 10 + s];
            os[n_l * 640 + t * 64 + hh * 8 + d] = a * inv;
        }
    }
    __syncthreads();
    int c = tid & 31, w = tid >> 5;
    float bias = bcs[c];
    const float* wrow = &wcs[c * 68];
    for (int p = w; p < 40; p += 8) {
        int n_l = p / 10, t = p - n_l * 10;
        const float* ob = &os[n_l * 640 + t * 64];
        float a = bias;
#pragma unroll
        for (int m = 0; m < 64; m += 4) {
            float4 wv = *(const float4*)&wrow[m];
            float4 o4 = *(const float4*)&ob[m];
            a += wv.x*o4.x + wv.y*o4.y + wv.z*o4.z + wv.w*o4.w;
        }
        g_xt[((b * 10 + t) * NN + n0 + n_l) * 32 + c] = a;
    }
}

__global__ void k_scores() {
    __shared__ float Xa[32 * 68], Xb[32 * 68], S[64 * 65];
    int bt = blockIdx.y;
    int bx = blockIdx.x;
    int ti = 0, rem = bx;
    while (rem >= 8 - ti) { rem -= 8 - ti; ti++; }
    int tj = ti + rem;
    int row0 = ti * 64, col0 = tj * 64;
    int tid = threadIdx.y * 16 + threadIdx.x;
    for (int idx = tid; idx < 2048; idx += 256) {
        int rl = idx >> 5, c = idx & 31;
        int r = row0 + rl, cc = col0 + rl;
        Xa[c * 68 + rl] = (r < NN) ? g_xt[(bt * NN + r) * 32 + c] : 0.f;
        Xb[c * 68 + rl] = (cc < NN) ? g_xt[(bt * NN + cc) * 32 + c] : 0.f;
    }
    __syncthreads();
    float acc[4][4] = {};
    int ra = threadIdx.y * 4, cb = threadIdx.x * 4;
#pragma unroll 8
    for (int v = 0; v < 32; v++) {
        float4 a = *(const float4*)&Xa[v * 68 + ra];
        float4 bb = *(const float4*)&Xb[v * 68 + cb];
        acc[0][0]+=a.x*bb.x; acc[0][1]+=a.x*bb.y; acc[0][2]+=a.x*bb.z; acc[0][3]+=a.x*bb.w;
        acc[1][0]+=a.y*bb.x; acc[1][1]+=a.y*bb.y; acc[1][2]+=a.y*bb.z; acc[1][3]+=a.y*bb.w;
        acc[2][0]+=a.z*bb.x; acc[2][1]+=a.z*bb.y; acc[2][2]+=a.z*bb.z; acc[2][3]+=a.z*bb.w;
        acc[3][0]+=a.w*bb.x; acc[3][1]+=a.w*bb.y; acc[3][2]+=a.w*bb.z; acc[3][3]+=a.w*bb.w;
    }
    const float scl = 0.17677669529663687f;
#pragma unroll
    for (int i = 0; i < 4; i++)
#pragma unroll
        for (int j = 0; j < 4; j++)
            S[(ra + i) * 65 + cb + j] = acc[i][j] * scl;
    __syncthreads();
    float* base = g_att + bt * 250000;
    for (int idx = tid; idx < 4096; idx += 256) {
        int rl = idx >> 6, cl = idx & 63;
        int r = row0 + rl, cc = col0 + cl;
        if (r < NN && cc < NN) base[r * 500 + cc] = S[rl * 65 + cl];
    }
    if (ti != tj) {
        for (int idx = tid; idx < 4096; idx += 256) {
            int rl = idx >> 6, cl = idx & 63;
            int r = col0 + rl, cc = row0 + cl;
            if (r < NN && cc < NN) base[r * 500 + cc] = S[cl * 65 + rl];
        }
    }
}

__global__ void k_softmax() {
    int bt = blockIdx.x, row = blockIdx.y * 8 + (threadIdx.x >> 5);
    if (row >= NN) return;
    int lane = threadIdx.x & 31;
    float4* p = (float4*)(g_att + bt * 250000 + row * 500);
    float4 vals[4];
    float mx = -1e30f;
#pragma unroll
    for (int ii = 0; ii < 4; ii++) {
        int m = lane + ii * 32;
        if (m < 125) {
            float4 v = p[m];
            vals[ii] = v;
            mx = fmaxf(mx, fmaxf(fmaxf(v.x, v.y), fmaxf(v.z, v.w)));
        }
    }
    for (int off = 16; off; off >>= 1) mx = fmaxf(mx, __shfl_xor_sync(~0u, mx, off));
    float s = 0.f;
#pragma unroll
    for (int ii = 0; ii < 4; ii++) {
        int m = lane + ii * 32;
        if (m < 125) {
            float4 v = vals[ii];
            v.x = expf(v.x - mx); v.y = expf(v.y - mx);
            v.z = expf(v.z - mx); v.w = expf(v.w - mx);
            vals[ii] = v;
            s += v.x + v.y + v.z + v.w;
        }
    }
    for (int off = 16; off; off >>= 1) s += __shfl_xor_sync(~0u, s, off);
    float inv = 1.f / s;
#pragma unroll
    for (int ii = 0; ii < 4; ii++) {
        int m = lane + ii * 32;
        if (m < 125) {
            float4 v = vals[ii];
            p[m] = make_float4(v.x * inv, v.y * inv, v.z * inv, v.w * inv);
        }
    }
}

__device__ __forceinline__ float* pick_buf(int s) {
    switch (s) { case 0: return g_xt; case 1: return g_z1; case 2: return g_z2;
                 case 3: return g_z3; default: return g_z4; }
}

__global__ void __launch_bounds__(256) k_gemm2(const float* A, int pass) {
    float* Ms = dynsm;
    float* Xs = dynsm + 4608;
    int bt = blockIdx.y, row0 = blockIdx.x * 128, tid = threadIdx.x;
    int z = blockIdx.z;
    const float* M = z ? (g_att + bt * 250000) : A;
    int xsel = pass ? (z ? 3 : 1) : 0;
    int ysel = pass ? (z ? 4 : 2) : (z ? 3 : 1);
    const float* X = pick_buf(xsel) + bt * 16000;
    float* Y = pick_buf(ysel) + bt * 16000;
    int rg = (tid >> 3) * 4, cg = (tid & 7) * 4;
    float acc[4][4] = {};
    for (int vb = 0; vb < 500; vb += 32) {
        for (int q4 = tid; q4 < 1024; q4 += 256) {
            int r = q4 >> 3, v4 = (q4 & 7) * 4;
            int gr = row0 + r, gv = vb + v4;
            float4 val = make_float4(0.f, 0.f, 0.f, 0.f);
            if (gr < 500 && gv < 500) val = *(const float4*)&M[gr * 500 + gv];
            *(float4*)&Ms[r * 36 + v4] = val;
        }
        {
            int v = tid >> 3, c4 = (tid & 7) * 4;
            float4 val = make_float4(0.f, 0.f, 0.f, 0.f);
            if (vb + v < 500) val = *(const float4*)&X[(vb + v) * 32 + c4];
            *(float4*)&Xs[v * 36 + c4] = val;
        }
        __syncthreads();
#pragma unroll
        for (int v4 = 0; v4 < 32; v4 += 4) {
            float4 x0 = *(const float4*)&Xs[(v4 + 0) * 36 + cg];
            float4 x1 = *(const float4*)&Xs[(v4 + 1) * 36 + cg];
            float4 x2 = *(const float4*)&Xs[(v4 + 2) * 36 + cg];
            float4 x3 = *(const float4*)&Xs[(v4 + 3) * 36 + cg];
#pragma unroll
            for (int i = 0; i < 4; i++) {
                float4 m = *(const float4*)&Ms[(rg + i) * 36 + v4];
                acc[i][0] += m.x*x0.x + m.y*x1.x + m.z*x2.x + m.w*x3.x;
                acc[i][1] += m.x*x0.y + m.y*x1.y + m.z*x2.y + m.w*x3.y;
                acc[i][2] += m.x*x0.z + m.y*x1.z + m.z*x2.z + m.w*x3.z;
                acc[i][3] += m.x*x0.w + m.y*x1.w + m.z*x2.w + m.w*x3.w;
            }
        }
        __syncthreads();
    }
#pragma unroll
    for (int i = 0; i < 4; i++) {
        int row = row0 + rg + i;
        if (row < 500)
            *(float4*)&Y[row * 32 + cg] = make_float4(acc[i][0], acc[i][1], acc[i][2], acc[i][3]);
    }
}

__global__ void k_mlp(const float* mw, const float* mb) {
    float* Ws = dynsm;
    float* Xs = dynsm + 10496;
    int bt = blockIdx.y, n0 = blockIdx.x * 32, tid = threadIdx.x;
    for (int i4 = tid; i4 < 2560; i4 += 256) {
        int row = i4 / 40, k4 = (i4 - row * 40) * 4;
        *(float4*)&Ws[row * 164 + k4] = *(const float4*)&mw[row * 160 + k4];
    }
    for (int i4 = tid; i4 < 1280; i4 += 256) {
        int nl = i4 / 40, k = i4 - nl * 40;
        int j = k >> 3, c4 = (k & 7) * 4;
        const float* src = (j==0)?g_xt:(j==1)?g_z1:(j==2)?g_z2:(j==3)?g_z3:g_z4;
        int n = n0 + nl;
        float4 val = make_float4(0.f, 0.f, 0.f, 0.f);
        if (n < 500) val = *(const float4*)&src[(bt * NN + n) * 32 + c4];
        *(float4*)&Xs[nl * 164 + j * 32 + c4] = val;
    }
    __syncthreads();
    int og = (tid >> 5) * 8, nl = tid & 31;
    float acc[8];
#pragma unroll
    for (int oo = 0; oo < 8; oo++) acc[oo] = mb[og + oo];
    for (int k4 = 0; k4 < 160; k4 += 4) {
        float4 x = *(const float4*)&Xs[nl * 164 + k4];
#pragma unroll
        for (int oo = 0; oo < 8; oo++) {
            float4 w = *(const float4*)&Ws[(og + oo) * 164 + k4];
            acc[oo] += w.x*x.x + w.y*x.y + w.z*x.z + w.w*x.w;
        }
    }
    __syncthreads();
    float* Outs = Xs;
#pragma unroll
    for (int oo = 0; oo < 8; oo++) Outs[nl * 64 + og + oo] = acc[oo];
    __syncthreads();
    for (int idx = tid; idx < 1024; idx += 256) {
        int nl2 = idx >> 5, c = idx & 31, n = n0 + nl2;
        if (n < 500) {
            float a = Outs[nl2 * 64 + c], bsg = Outs[nl2 * 64 + c + 32];
            g_g[(bt * NN + n) * 32 + c] = tanhf(a) * (1.f / (1.f + expf(-bsg)));
        }
    }
}

__global__ void k_ct1(const float* w, const float* bb) {
    __shared__ float ws[60], bs[6];
    if (threadIdx.x < 60) ws[threadIdx.x] = w[threadIdx.x];
    if (threadIdx.x < 6) bs[threadIdx.x] = bb[threadIdx.x];
    __syncthreads();
    int idx = blockIdx.x * 256 + threadIdx.x;
    if (idx >= 256000) return;
    int b = idx / 16000, rem = idx - b * 16000, c = rem / 500, n = rem - c * 500;
    float gv[10];
#pragma unroll
    for (int t = 0; t < 10; t++) gv[t] = g_g[((b * 10 + t) * NN + n) * 32 + c];
    int ob = ((b * 32 + c) * NN + n) * 6;
#pragma unroll
    for (int s = 0; s < 6; s++) {
        float a = bs[s];
#pragma unroll
        for (int t = 0; t < 10; t++) a += ws[s * 10 + t] * gv[t];
        g_g6[ob + s] = a;
    }
}

__global__ void k_tatt(const float* c1W, const float* c2W, const float* tw,
                       const float* tb, const float* tv) {
    __shared__ float f1s[3000], f2s[192], tmps[192], c1s[32], c2s[500], lg[36];
    int b = blockIdx.x, tid = threadIdx.x;
    if (tid < 32) c1s[tid] = c1W[tid];
    for (int i = tid; i < 500; i += 256) c2s[i] = c2W[i];
    __syncthreads();
    for (int i = tid; i < 3000; i += 256) {
        int t = i / 500, n = i - t * 500;
        float s = 0.f;
        for (int c = 0; c < 32; c++) s += g_g6[((b * 32 + c) * NN + n) * 6 + t] * c1s[c];
        f1s[t * 500 + n] = s;
    }
    if (tid < 192) {
        int c = tid / 6, s = tid - c * 6;
        float a = 0.f;
        for (int n = 0; n < 500; n++) a += g_g6[((b * 32 + c) * NN + n) * 6 + s] * c2s[n];
        f2s[c * 6 + s] = a;
    }
    __syncthreads();
    if (tid < 192) {
        int t = tid / 32, c = tid & 31;
        float a = 0.f;
        for (int n = 0; n < 500; n++) a += f1s[t * 500 + n] * tw[n * 32 + c];
        tmps[t * 32 + c] = a;
    }
    __syncthreads();
    if (tid < 36) {
        int t = tid / 6, s = tid - t * 6;
        float a = tb[t * 6 + s];
        for (int c = 0; c < 32; c++) a += tmps[t * 32 + c] * f2s[c * 6 + s];
        lg[t * 6 + s] = 1.f / (1.f + expf(-a));
    }
    __syncthreads();
    if (tid < 36) {
        int p = tid / 6, s = tid - p * 6;
        float a = 0.f;
        for (int t = 0; t < 6; t++) a += tv[p * 6 + t] * lg[t * 6 + s];
        g_lp[b * 36 + p * 6 + s] = a;
    }
}

__global__ void k_bn1(const float* g1, const float* b1) {
    __shared__ float ms[6], iv[6];
    int tid = threadIdx.x;
    if (tid < 6) {
        float s = 0.f, s2 = 0.f;
        for (int b = 0; b < 16; b++)
            for (int p = 0; p < 6; p++) {
                float v = g_lp[b * 36 + p * 6 + tid];
                s += v; s2 += v * v;
            }
        float mu = s / 96.f, var = s2 / 96.f - mu * mu;
        ms[tid] = mu; iv[tid] = rsqrtf(var + 1e-5f);
    }
    __syncthreads();
    if (tid < 96) {
        int b = tid / 6, q = tid - b * 6;
        float v[6], mx = -1e30f;
#pragma unroll
        for (int l = 0; l < 6; l++) {
            v[l] = (g_lp[b * 36 + q * 6 + l] - ms[l]) * iv[l] * g1[l] + b1[l];
            mx = fmaxf(mx, v[l]);
        }
        float s = 0.f;
#pragma unroll
        for (int l = 0; l < 6; l++) { v[l] = expf(v[l] - mx); s += v[l]; }
        float inv = 1.f / s;
#pragma unroll
        for (int l = 0; l < 6; l++) g_Tc[b * 36 + l * 6 + q] = v[l] * inv;
    }
}

__global__ void k_xo(float* out) {
    __shared__ float ssum[256], ssq[256], tcs[36];
    int b = blockIdx.y, nc = blockIdx.x, tid = threadIdx.x;
    int c = tid >> 3, w = tid & 7;
    if (tid < 36) tcs[tid] = g_Tc[b * 36 + tid];
    __syncthreads();
    float s1 = 0.f, s2 = 0.f;
    for (int j = 0; j < 24; j++) {
        int e = w * 24 + j, n_l = e / 6, q = e - n_l * 6, n = nc * 32 + n_l;
        if (n >= 500) continue;
        int gi = ((b * 32 + c) * NN + n) * 6;
        float a = 0.f;
#pragma unroll
        for (int l = 0; l < 6; l++) a += g_g6[gi + l] * tcs[l * 6 + q];
        a = (a > 0.f) ? a : 0.01f * a;
        a += g_resid[(b * 32 + c) * NPOS + n * 10 + 4 + q];
        out[gi + q] = a;
        s1 += a; s2 += a * a;
    }
    ssum[tid] = s1; ssq[tid] = s2;
    __syncthreads();
    if (w == 0) {
        float a = 0.f, aa = 0.f;
        for (int k = 0; k < 8; k++) { a += ssum[c * 8 + k]; aa += ssq[c * 8 + k]; }
        int blk = b * 16 + nc;
        g_part[blk * 32 + c] = a;
        g_part[8192 + blk * 32 + c] = aa;
    }
}

__global__ void k_bn2stats(const float* g2, const float* b2) {
    int c = threadIdx.x;
    if (c >= 32) return;
    float s = 0.f, s2 = 0.f;
    for (int i = 0; i < 256; i++) { s += g_part[i * 32 + c]; s2 += g_part[8192 + i * 32 + c]; }
    float mu = s / 48000.f, var = s2 / 48000.f - mu * mu;
    float scale = g2[c] * rsqrtf(var + 1e-5f);
    g_stats[c] = scale;
    g_stats[32 + c] = b2[c] - mu * scale;
}

__global__ void k_bn2apply(float* out) {
    int i = blockIdx.x * 256 + threadIdx.x;
    if (i >= 1536000) return;
    int c = (i / 3000) & 31;
    out[i] = out[i] * g_stats[c] + g_stats[32 + c];
}

extern "C" void kernel_launch(void* const* d_in, const int* in_sizes, int n_in,
                              void* d_out, int out_size) {
    const float *x = (const float*)d_in[0], *A = (const float*)d_in[1];
    const float *c1W = (const float*)d_in[2], *c1b = (const float*)d_in[3];
    const float *t1W = (const float*)d_in[4], *t1b = (const float*)d_in[5];
    const float *qW = (const float*)d_in[6], *qb = (const float*)d_in[7];
    const float *kW = (const float*)d_in[8], *kb = (const float*)d_in[9];
    const float *vW = (const float*)d_in[10], *vb = (const float*)d_in[11];
    const float *oW = (const float*)d_in[12], *ob = (const float*)d_in[13];
    const float *t2W = (const float*)d_in[14], *t2b = (const float*)d_in[15];
    const float *mW = (const float*)d_in[16], *mb = (const float*)d_in[17];
    const float *ctW = (const float*)d_in[18], *ctb = (const float*)d_in[19];
    const float *tc1 = (const float*)d_in[20], *tc2 = (const float*)d_in[21];
    const float *tw = (const float*)d_in[22], *tb = (const float*)d_in[23];
    const float *tv = (const float*)d_in[24];
    const float *b1g = (const float*)d_in[25], *b1b = (const float*)d_in[26];
    const float *b2g = (const float*)d_in[27], *b2b = (const float*)d_in[28];
    float* out = (float*)d_out;

    static int configured = 0;
    if (!configured) {
        cudaFuncSetAttribute(k_qkv, cudaFuncAttributeMaxDynamicSharedMemorySize, 49152);
        cudaFuncSetAttribute(k_mlp, cudaFuncAttributeMaxDynamicSharedMemorySize, 63488);
        cudaFuncSetAttribute(k_attn, cudaFuncAttributeMaxDynamicSharedMemorySize, 49792);
        cudaFuncSetAttribute(k_gemm2, cudaFuncAttributeMaxDynamicSharedMemorySize, 23040);
        configured = 1;
    }

    k_wprep<<<70, 256>>>(qW, kW, vW, t1W, t1b, qb, kb, vb, t2W, oW, ob, t2b);
    k_conv1<<<dim3(16, 20), 256>>>(x, c1W, c1b);
    k_qkv<<<dim3(16, 79), 256, 49152>>>(x);
    k_attn<<<dim3(125, 16), 256, 49792>>>();
    k_scores<<<dim3(36, 160), dim3(16, 16)>>>();
    k_softmax<<<dim3(160, 63), 256>>>();
    k_gemm2<<<dim3(4, 160, 2), 256, 23040>>>(A, 0);
    k_gemm2<<<dim3(4, 160, 2), 256, 23040>>>(A, 1);
    k_mlp<<<dim3(16, 160), 256, 63488>>>(mW, mb);
    k_ct1<<<1000, 256>>>(ctW, ctb);
    k_tatt<<<16, 256>>>(tc1, tc2, tw, tb, tv);
    k_bn1<<<1, 128>>>(b1g, b1b);
    k_xo<<<dim3(16, 16), 256>>>(out);
    k_bn2stats<<<1, 32>>>(b2g, b2b);
    k_bn2apply<<<6000, 256>>>(out);
}

// round 17
// speedup vs baseline: 1.1539x; 1.1539x over previous
#include <cuda_runtime.h>
#include <math.h>

#define NPOS 5000
#define NN 500

__device__ float g_q[16*64*5000];
__device__ float g_k[16*64*5000];
__device__ float g_v[16*64*5000];
__device__ float g_resid[16*32*5000];
__device__ float g_xt[160*500*32];
__device__ float g_att[160*500*500];
__device__ float g_z1[160*500*32];
__device__ float g_z2[160*500*32];
__device__ float g_z3[160*500*32];
__device__ float g_z4[160*500*32];
__device__ float g_g[160*500*32];
__device__ float g_g6[16*32*500*6];
__device__ float g_lp[16*36];
__device__ float g_Tc[16*36];
__device__ float g_wqT[96*64];
__device__ float g_wkT[96*64];
__device__ float g_wvT[32*64];
__device__ float g_qb2[640];
__device__ float g_kb2[640];
__device__ float g_vb2[640];
__device__ float g_Wc[32*64];
__device__ float g_bc[32];
__device__ float g_part[16384];
__device__ float g_stats[64];

__global__ void k_wprep(const float* wq, const float* wk, const float* linv,
                        const float* te1, const float* te1b,
                        const float* qb, const float* kb, const float* vb,
                        const float* te2, const float* lino, const float* lino_b,
                        const float* te2_b) {
    int idx = blockIdx.x * 256 + threadIdx.x;
    if (idx < 6144) {
        int kk = idx >> 6, o = idx & 63, c = kk / 3, r = kk - c * 3;
        float s = 0.f;
        for (int i = 0; i < 64; i++) s += wq[(o * 64 + i) * 3 + r] * te1[i * 32 + c];
        g_wqT[idx] = s; return;
    }
    idx -= 6144;
    if (idx < 6144) {
        int kk = idx >> 6, o = idx & 63, c = kk / 3, r = kk - c * 3;
        float s = 0.f;
        for (int i = 0; i < 64; i++) s += wk[(o * 64 + i) * 3 + r] * te1[i * 32 + c];
        g_wkT[idx] = s; return;
    }
    idx -= 6144;
    if (idx < 2048) {
        int c = idx >> 6, o = idx & 63;
        float s = 0.f;
        for (int i = 0; i < 64; i++) s += linv[o * 64 + i] * te1[i * 32 + c];
        g_wvT[idx] = s; return;
    }
    idx -= 2048;
    if (idx < 640) {
        int o = idx / 10, t = idx - o * 10;
        float s = qb[o];
        for (int r = 0; r < 3; r++) {
            int tt = t + r - 1;
            if (tt >= 0 && tt < 10)
                for (int i = 0; i < 64; i++) s += wq[(o * 64 + i) * 3 + r] * te1b[i];
        }
        g_qb2[idx] = s; return;
    }
    idx -= 640;
    if (idx < 640) {
        int o = idx / 10, t = idx - o * 10;
        float s = kb[o];
        for (int r = 0; r < 3; r++) {
            int tt = t + r - 1;
            if (tt >= 0 && tt < 10)
                for (int i = 0; i < 64; i++) s += wk[(o * 64 + i) * 3 + r] * te1b[i];
        }
        g_kb2[idx] = s; return;
    }
    idx -= 640;
    if (idx < 640) {
        int o = idx / 10;
        float s = vb[o];
        for (int i = 0; i < 64; i++) s += linv[o * 64 + i] * te1b[i];
        g_vb2[idx] = s; return;
    }
    idx -= 640;
    if (idx < 2048) {
        int o = idx >> 6, m = idx & 63;
        float s = 0.f;
        for (int j = 0; j < 64; j++) s += te2[o * 64 + j] * lino[j * 64 + m];
        g_Wc[idx] = s; return;
    }
    idx -= 2048;
    if (idx < 32) {
        float s = te2_b[idx];
        for (int j = 0; j < 64; j++) s += te2[idx * 64 + j] * lino_b[j];
        g_bc[idx] = s;
    }
}

__global__ void k_conv1(const float* x, const float* w1, const float* b1) {
    __shared__ float w1s[1024], b1s[32];
    int tid = threadIdx.x;
    for (int i = tid; i < 1024; i += 256) w1s[i] = w1[i];
    if (tid < 32) b1s[tid] = b1[tid];
    __syncthreads();
    int b = blockIdx.x, pos = blockIdx.y * 256 + tid;
    if (pos >= NPOS) return;
    float xv[32];
#pragma unroll
    for (int c = 0; c < 32; c++) xv[c] = x[(b * 32 + c) * NPOS + pos];
    for (int o = 0; o < 32; o++) {
        float a = b1s[o];
#pragma unroll
        for (int c = 0; c < 32; c++) a += w1s[o * 32 + c] * xv[c];
        g_resid[(b * 32 + o) * NPOS + pos] = a;
    }
}

extern __shared__ float dynsm[];
__device__ __forceinline__ void qkv_gemm(const float* hsh, const float* ws, int nk,
                                          const float* bias, float* out, int b,
                                          int pos0, int o0, int p0, int stride) {
    float4 a0 = {0,0,0,0}, a1 = a0, a2 = a0, a3 = a0;
    for (int kk = 0; kk < nk; kk++) {
        float4 w = *(const float4*)&ws[kk * 64 + o0];
        float4 xx = *(const float4*)&hsh[kk * stride * 64 + p0];
        a0.x += w.x*xx.x; a0.y += w.x*xx.y; a0.z += w.x*xx.z; a0.w += w.x*xx.w;
        a1.x += w.y*xx.x; a1.y += w.y*xx.y; a1.z += w.y*xx.z; a1.w += w.y*xx.w;
        a2.x += w.z*xx.x; a2.y += w.z*xx.y; a2.z += w.z*xx.z; a2.w += w.z*xx.w;
        a3.x += w.w*xx.x; a3.y += w.w*xx.y; a3.z += w.w*xx.z; a3.w += w.w*xx.w;
    }
    int pos = pos0 + p0;
    if (pos < NPOS) {
        int t0 = pos % 10;
        int t1 = (t0 + 1) % 10, t2 = (t0 + 2) % 10, t3 = (t0 + 3) % 10;
        int base = (b * 64 + o0) * NPOS + pos;
        float acc[4][4] = {{a0.x,a0.y,a0.z,a0.w},{a1.x,a1.y,a1.z,a1.w},
                           {a2.x,a2.y,a2.z,a2.w},{a3.x,a3.y,a3.z,a3.w}};
#pragma unroll
        for (int r = 0; r < 4; r++) {
            const float* brow = &bias[(o0 + r) * 10];
            *(float4*)&out[base + r * NPOS] = make_float4(
                acc[r][0] + brow[t0], acc[r][1] + brow[t1],
                acc[r][2] + brow[t2], acc[r][3] + brow[t3]);
        }
    }
}

__global__ void __launch_bounds__(256) k_qkv(const float* x) {
    float* hsh = dynsm;
    float* ws  = dynsm + 6144;
    int b = blockIdx.x, pos0 = blockIdx.y * 64, tid = threadIdx.x;
    for (int idx = tid; idx < 6144; idx += 256) {
        int kk = idx >> 6, pl = idx & 63, c = kk / 3, r = kk - c * 3;
        int pos = pos0 + pl; float v = 0.f;
        if (pos < NPOS) {
            int t = pos % 10, tt = t + r - 1;
            if (tt >= 0 && tt < 10) v = x[(b * 32 + c) * NPOS + pos + r - 1];
        }
        hsh[idx] = v;
    }
    int o0 = (tid >> 4) * 4, p0 = (tid & 15) * 4;
    for (int idx = tid; idx < 6144; idx += 256) ws[idx] = g_wqT[idx];
    __syncthreads();
    qkv_gemm(hsh, ws, 96, g_qb2, g_q, b, pos0, o0, p0, 1);
    __syncthreads();
    for (int idx = tid; idx < 6144; idx += 256) ws[idx] = g_wkT[idx];
    __syncthreads();
    qkv_gemm(hsh, ws, 96, g_kb2, g_k, b, pos0, o0, p0, 1);
    __syncthreads();
    for (int idx = tid; idx < 2048; idx += 256) ws[idx] = g_wvT[idx];
    __syncthreads();
    qkv_gemm(hsh + 64, ws, 32, g_vb2, g_v, b, pos0, o0, p0, 3);
}

__global__ void __launch_bounds__(256) k_attn() {
    float* qs = dynsm;
    float* ks = dynsm + 2560;
    float* vs = dynsm + 5120;
    float* os = dynsm + 7680;
    float* wcs = dynsm + 10240;
    float* bcs = dynsm + 12416;
    int n0 = blockIdx.x * 4, b = blockIdx.y, tid = threadIdx.x;
    for (int idx = tid; idx < 2560; idx += 256) {
        int n_l = idx / 640, rem = idx - n_l * 640;
        int ch = rem / 10, t = rem - ch * 10;
        int gi = b * 64 * NPOS + ch * NPOS + (n0 + n_l) * 10 + t;
        qs[idx] = g_q[gi]; ks[idx] = g_k[gi]; vs[idx] = g_v[gi];
    }
    for (int idx = tid; idx < 2048; idx += 256) {
        int c = idx >> 6, m = idx & 63;
        wcs[c * 68 + m] = g_Wc[idx];
    }
    if (tid < 32) bcs[tid] = g_bc[tid];
    __syncthreads();
    for (int u = tid; u < 320; u += 256) {
        int n_l = u / 80, r = u - n_l * 80;
        int hh = r / 10, t = r - hh * 10;
        int qb = n_l * 640 + hh * 80;
        float qv[8], sc[10];
#pragma unroll
        for (int d = 0; d < 8; d++) qv[d] = qs[qb + d * 10 + t];
#pragma unroll
        for (int s = 0; s < 10; s++) {
            float a = 0.f;
#pragma unroll
            for (int d = 0; d < 8; d++) a += qv[d] * ks[qb + d * 10 + s];
            sc[s] = a * 0.35355339059327373f;
        }
        float mx = sc[0];
#pragma unroll
        for (int s = 1; s < 10; s++) mx = fmaxf(mx, sc[s]);
        float sum = 0.f;
#pragma unroll
        for (int s = 0; s < 10; s++) { sc[s] = expf(sc[s] - mx); sum += sc[s]; }
        float inv = 1.f / sum;
#pragma unroll
        for (int d = 0; d < 8; d++) {
            float a = 0.f;
#pragma unroll
            for (int s = 0; s < 10; s++) a += sc[s] * vs[qb + d * 10 + s];
            os[n_l * 640 + t * 64 + hh * 8 + d] = a * inv;
        }
    }
    __syncthreads();
    int c = tid & 31, w = tid >> 5;
    float bias = bcs[c];
    const float* wrow = &wcs[c * 68];
    for (int p = w; p < 40; p += 8) {
        int n_l = p / 10, t = p - n_l * 10;
        const float* ob = &os[n_l * 640 + t * 64];
        float a = bias;
#pragma unroll
        for (int m = 0; m < 64; m += 4) {
            float4 wv = *(const float4*)&wrow[m];
            float4 o4 = *(const float4*)&ob[m];
            a += wv.x*o4.x + wv.y*o4.y + wv.z*o4.z + wv.w*o4.w;
        }
        g_xt[((b * 10 + t) * NN + n0 + n_l) * 32 + c] = a;
    }
}

__global__ void k_scores() {
    __shared__ float Xa[32 * 68], Xb[32 * 68], S[64 * 65];
    int bt = blockIdx.y;
    int bx = blockIdx.x;
    int ti = 0, rem = bx;
    while (rem >= 8 - ti) { rem -= 8 - ti; ti++; }
    int tj = ti + rem;
    int row0 = ti * 64, col0 = tj * 64;
    int tid = threadIdx.y * 16 + threadIdx.x;
    for (int idx = tid; idx < 2048; idx += 256) {
        int rl = idx >> 5, c = idx & 31;
        int r = row0 + rl, cc = col0 + rl;
        Xa[c * 68 + rl] = (r < NN) ? g_xt[(bt * NN + r) * 32 + c] : 0.f;
        Xb[c * 68 + rl] = (cc < NN) ? g_xt[(bt * NN + cc) * 32 + c] : 0.f;
    }
    __syncthreads();
    float acc[4][4] = {};
    int ra = threadIdx.y * 4, cb = threadIdx.x * 4;
#pragma unroll 8
    for (int v = 0; v < 32; v++) {
        float4 a = *(const float4*)&Xa[v * 68 + ra];
        float4 bb = *(const float4*)&Xb[v * 68 + cb];
        acc[0][0]+=a.x*bb.x; acc[0][1]+=a.x*bb.y; acc[0][2]+=a.x*bb.z; acc[0][3]+=a.x*bb.w;
        acc[1][0]+=a.y*bb.x; acc[1][1]+=a.y*bb.y; acc[1][2]+=a.y*bb.z; acc[1][3]+=a.y*bb.w;
        acc[2][0]+=a.z*bb.x; acc[2][1]+=a.z*bb.y; acc[2][2]+=a.z*bb.z; acc[2][3]+=a.z*bb.w;
        acc[3][0]+=a.w*bb.x; acc[3][1]+=a.w*bb.y; acc[3][2]+=a.w*bb.z; acc[3][3]+=a.w*bb.w;
    }
    const float scl = 0.17677669529663687f;
#pragma unroll
    for (int i = 0; i < 4; i++)
#pragma unroll
        for (int j = 0; j < 4; j++)
            S[(ra + i) * 65 + cb + j] = acc[i][j] * scl;
    __syncthreads();
    float* base = g_att + bt * 250000;
    for (int idx = tid; idx < 4096; idx += 256) {
        int rl = idx >> 6, cl = idx & 63;
        int r = row0 + rl, cc = col0 + cl;
        if (r < NN && cc < NN) base[r * 500 + cc] = S[rl * 65 + cl];
    }
    if (ti != tj) {
        for (int idx = tid; idx < 4096; idx += 256) {
            int rl = idx >> 6, cl = idx & 63;
            int r = col0 + rl, cc = row0 + cl;
            if (r < NN && cc < NN) base[r * 500 + cc] = S[cl * 65 + rl];
        }
    }
}

__global__ void k_softmax() {
    int bt = blockIdx.x, row = blockIdx.y * 8 + (threadIdx.x >> 5);
    if (row >= NN) return;
    int lane = threadIdx.x & 31;
    float4* p = (float4*)(g_att + bt * 250000 + row * 500);
    float4 vals[4];
    float mx = -1e30f;
#pragma unroll
    for (int ii = 0; ii < 4; ii++) {
        int m = lane + ii * 32;
        if (m < 125) {
            float4 v = p[m];
            vals[ii] = v;
            mx = fmaxf(mx, fmaxf(fmaxf(v.x, v.y), fmaxf(v.z, v.w)));
        }
    }
    for (int off = 16; off; off >>= 1) mx = fmaxf(mx, __shfl_xor_sync(~0u, mx, off));
    float s = 0.f;
#pragma unroll
    for (int ii = 0; ii < 4; ii++) {
        int m = lane + ii * 32;
        if (m < 125) {
            float4 v = vals[ii];
            v.x = expf(v.x - mx); v.y = expf(v.y - mx);
            v.z = expf(v.z - mx); v.w = expf(v.w - mx);
            vals[ii] = v;
            s += v.x + v.y + v.z + v.w;
        }
    }
    for (int off = 16; off; off >>= 1) s += __shfl_xor_sync(~0u, s, off);
    float inv = 1.f / s;
#pragma unroll
    for (int ii = 0; ii < 4; ii++) {
        int m = lane + ii * 32;
        if (m < 125) {
            float4 v = vals[ii];
            p[m] = make_float4(v.x * inv, v.y * inv, v.z * inv, v.w * inv);
        }
    }
}

__device__ __forceinline__ float* pick_buf(int s) {
    switch (s) { case 0: return g_xt; case 1: return g_z1; case 2: return g_z2;
                 case 3: return g_z3; default: return g_z4; }
}

// 5 blocks/SM target: m-float4s loaded per v4, one x-float4 live at a time
__global__ void __launch_bounds__(256, 5) k_gemm2(const float* A, int pass) {
    float* Ms = dynsm;
    float* Xs = dynsm + 4608;
    int bt = blockIdx.y, row0 = blockIdx.x * 128, tid = threadIdx.x;
    int z = blockIdx.z;
    const float* M = z ? (g_att + bt * 250000) : A;
    int xsel = pass ? (z ? 3 : 1) : 0;
    int ysel = pass ? (z ? 4 : 2) : (z ? 3 : 1);
    const float* X = pick_buf(xsel) + bt * 16000;
    float* Y = pick_buf(ysel) + bt * 16000;
    int rg = (tid >> 3) * 4, cg = (tid & 7) * 4;
    float acc[4][4] = {};
    for (int vb = 0; vb < 500; vb += 32) {
        for (int q4 = tid; q4 < 1024; q4 += 256) {
            int r = q4 >> 3, v4 = (q4 & 7) * 4;
            int gr = row0 + r, gv = vb + v4;
            float4 val = make_float4(0.f, 0.f, 0.f, 0.f);
            if (gr < 500 && gv < 500) val = *(const float4*)&M[gr * 500 + gv];
            *(float4*)&Ms[r * 36 + v4] = val;
        }
        {
            int v = tid >> 3, c4 = (tid & 7) * 4;
            float4 val = make_float4(0.f, 0.f, 0.f, 0.f);
            if (vb + v < 500) val = *(const float4*)&X[(vb + v) * 32 + c4];
            *(float4*)&Xs[v * 36 + c4] = val;
        }
        __syncthreads();
#pragma unroll
        for (int v4 = 0; v4 < 32; v4 += 4) {
            float4 m0 = *(const float4*)&Ms[(rg + 0) * 36 + v4];
            float4 m1 = *(const float4*)&Ms[(rg + 1) * 36 + v4];
            float4 m2 = *(const float4*)&Ms[(rg + 2) * 36 + v4];
            float4 m3 = *(const float4*)&Ms[(rg + 3) * 36 + v4];
            {
                float4 x = *(const float4*)&Xs[(v4 + 0) * 36 + cg];
                acc[0][0]+=m0.x*x.x; acc[0][1]+=m0.x*x.y; acc[0][2]+=m0.x*x.z; acc[0][3]+=m0.x*x.w;
                acc[1][0]+=m1.x*x.x; acc[1][1]+=m1.x*x.y; acc[1][2]+=m1.x*x.z; acc[1][3]+=m1.x*x.w;
                acc[2][0]+=m2.x*x.x; acc[2][1]+=m2.x*x.y; acc[2][2]+=m2.x*x.z; acc[2][3]+=m2.x*x.w;
                acc[3][0]+=m3.x*x.x; acc[3][1]+=m3.x*x.y; acc[3][2]+=m3.x*x.z; acc[3][3]+=m3.x*x.w;
            }
            {
                float4 x = *(const float4*)&Xs[(v4 + 1) * 36 + cg];
                acc[0][0]+=m0.y*x.x; acc[0][1]+=m0.y*x.y; acc[0][2]+=m0.y*x.z; acc[0][3]+=m0.y*x.w;
                acc[1][0]+=m1.y*x.x; acc[1][1]+=m1.y*x.y; acc[1][2]+=m1.y*x.z; acc[1][3]+=m1.y*x.w;
                acc[2][0]+=m2.y*x.x; acc[2][1]+=m2.y*x.y; acc[2][2]+=m2.y*x.z; acc[2][3]+=m2.y*x.w;
                acc[3][0]+=m3.y*x.x; acc[3][1]+=m3.y*x.y; acc[3][2]+=m3.y*x.z; acc[3][3]+=m3.y*x.w;
            }
            {
                float4 x = *(const float4*)&Xs[(v4 + 2) * 36 + cg];
                acc[0][0]+=m0.z*x.x; acc[0][1]+=m0.z*x.y; acc[0][2]+=m0.z*x.z; acc[0][3]+=m0.z*x.w;
                acc[1][0]+=m1.z*x.x; acc[1][1]+=m1.z*x.y; acc[1][2]+=m1.z*x.z; acc[1][3]+=m1.z*x.w;
                acc[2][0]+=m2.z*x.x; acc[2][1]+=m2.z*x.y; acc[2][2]+=m2.z*x.z; acc[2][3]+=m2.z*x.w;
                acc[3][0]+=m3.z*x.x; acc[3][1]+=m3.z*x.y; acc[3][2]+=m3.z*x.z; acc[3][3]+=m3.z*x.w;
            }
            {
                float4 x = *(const float4*)&Xs[(v4 + 3) * 36 + cg];
                acc[0][0]+=m0.w*x.x; acc[0][1]+=m0.w*x.y; acc[0][2]+=m0.w*x.z; acc[0][3]+=m0.w*x.w;
                acc[1][0]+=m1.w*x.x; acc[1][1]+=m1.w*x.y; acc[1][2]+=m1.w*x.z; acc[1][3]+=m1.w*x.w;
                acc[2][0]+=m2.w*x.x; acc[2][1]+=m2.w*x.y; acc[2][2]+=m2.w*x.z; acc[2][3]+=m2.w*x.w;
                acc[3][0]+=m3.w*x.x; acc[3][1]+=m3.w*x.y; acc[3][2]+=m3.w*x.z; acc[3][3]+=m3.w*x.w;
            }
        }
        __syncthreads();
    }
#pragma unroll
    for (int i = 0; i < 4; i++) {
        int row = row0 + rg + i;
        if (row < 500)
            *(float4*)&Y[row * 32 + cg] = make_float4(acc[i][0], acc[i][1], acc[i][2], acc[i][3]);
    }
}

__global__ void k_mlp(const float* mw, const float* mb) {
    float* Ws = dynsm;
    float* Xs = dynsm + 10496;
    int bt = blockIdx.y, n0 = blockIdx.x * 32, tid = threadIdx.x;
    for (int i4 = tid; i4 < 2560; i4 += 256) {
        int row = i4 / 40, k4 = (i4 - row * 40) * 4;
        *(float4*)&Ws[row * 164 + k4] = *(const float4*)&mw[row * 160 + k4];
    }
    for (int i4 = tid; i4 < 1280; i4 += 256) {
        int nl = i4 / 40, k = i4 - nl * 40;
        int j = k >> 3, c4 = (k & 7) * 4;
        const float* src = (j==0)?g_xt:(j==1)?g_z1:(j==2)?g_z2:(j==3)?g_z3:g_z4;
        int n = n0 + nl;
        float4 val = make_float4(0.f, 0.f, 0.f, 0.f);
        if (n < 500) val = *(const float4*)&src[(bt * NN + n) * 32 + c4];
        *(float4*)&Xs[nl * 164 + j * 32 + c4] = val;
    }
    __syncthreads();
    int og = (tid >> 5) * 8, nl = tid & 31;
    float acc[8];
#pragma unroll
    for (int oo = 0; oo < 8; oo++) acc[oo] = mb[og + oo];
    for (int k4 = 0; k4 < 160; k4 += 4) {
        float4 x = *(const float4*)&Xs[nl * 164 + k4];
#pragma unroll
        for (int oo = 0; oo < 8; oo++) {
            float4 w = *(const float4*)&Ws[(og + oo) * 164 + k4];
            acc[oo] += w.x*x.x + w.y*x.y + w.z*x.z + w.w*x.w;
        }
    }
    __syncthreads();
    float* Outs = Xs;
#pragma unroll
    for (int oo = 0; oo < 8; oo++) Outs[nl * 64 + og + oo] = acc[oo];
    __syncthreads();
    for (int idx = tid; idx < 1024; idx += 256) {
        int nl2 = idx >> 5, c = idx & 31, n = n0 + nl2;
        if (n < 500) {
            float a = Outs[nl2 * 64 + c], bsg = Outs[nl2 * 64 + c + 32];
            g_g[(bt * NN + n) * 32 + c] = tanhf(a) * (1.f / (1.f + expf(-bsg)));
        }
    }
}

__global__ void k_ct1(const float* w, const float* bb) {
    __shared__ float ws[60], bs[6];
    if (threadIdx.x < 60) ws[threadIdx.x] = w[threadIdx.x];
    if (threadIdx.x < 6) bs[threadIdx.x] = bb[threadIdx.x];
    __syncthreads();
    int idx = blockIdx.x * 256 + threadIdx.x;
    if (idx >= 256000) return;
    int b = idx / 16000, rem = idx - b * 16000, c = rem / 500, n = rem - c * 500;
    float gv[10];
#pragma unroll
    for (int t = 0; t < 10; t++) gv[t] = g_g[((b * 10 + t) * NN + n) * 32 + c];
    int ob = ((b * 32 + c) * NN + n) * 6;
#pragma unroll
    for (int s = 0; s < 6; s++) {
        float a = bs[s];
#pragma unroll
        for (int t = 0; t < 10; t++) a += ws[s * 10 + t] * gv[t];
        g_g6[ob + s] = a;
    }
}

__global__ void k_tatt(const float* c1W, const float* c2W, const float* tw,
                       const float* tb, const float* tv) {
    __shared__ float f1s[3000], f2s[192], tmps[192], c1s[32], c2s[500], lg[36];
    int b = blockIdx.x, tid = threadIdx.x;
    if (tid < 32) c1s[tid] = c1W[tid];
    for (int i = tid; i < 500; i += 256) c2s[i] = c2W[i];
    __syncthreads();
    for (int i = tid; i < 3000; i += 256) {
        int t = i / 500, n = i - t * 500;
        float s = 0.f;
        for (int c = 0; c < 32; c++) s += g_g6[((b * 32 + c) * NN + n) * 6 + t] * c1s[c];
        f1s[t * 500 + n] = s;
    }
    if (tid < 192) {
        int c = tid / 6, s = tid - c * 6;
        float a = 0.f;
        for (int n = 0; n < 500; n++) a += g_g6[((b * 32 + c) * NN + n) * 6 + s] * c2s[n];
        f2s[c * 6 + s] = a;
    }
    __syncthreads();
    if (tid < 192) {
        int t = tid / 32, c = tid & 31;
        float a = 0.f;
        for (int n = 0; n < 500; n++) a += f1s[t * 500 + n] * tw[n * 32 + c];
        tmps[t * 32 + c] = a;
    }
    __syncthreads();
    if (tid < 36) {
        int t = tid / 6, s = tid - t * 6;
        float a = tb[t * 6 + s];
        for (int c = 0; c < 32; c++) a += tmps[t * 32 + c] * f2s[c * 6 + s];
        lg[t * 6 + s] = 1.f / (1.f + expf(-a));
    }
    __syncthreads();
    if (tid < 36) {
        int p = tid / 6, s = tid - p * 6;
        float a = 0.f;
        for (int t = 0; t < 6; t++) a += tv[p * 6 + t] * lg[t * 6 + s];
        g_lp[b * 36 + p * 6 + s] = a;
    }
}

__global__ void k_bn1(const float* g1, const float* b1) {
    __shared__ float ms[6], iv[6];
    int tid = threadIdx.x;
    if (tid < 6) {
        float s = 0.f, s2 = 0.f;
        for (int b = 0; b < 16; b++)
            for (int p = 0; p < 6; p++) {
                float v = g_lp[b * 36 + p * 6 + tid];
                s += v; s2 += v * v;
            }
        float mu = s / 96.f, var = s2 / 96.f - mu * mu;
        ms[tid] = mu; iv[tid] = rsqrtf(var + 1e-5f);
    }
    __syncthreads();
    if (tid < 96) {
        int b = tid / 6, q = tid - b * 6;
        float v[6], mx = -1e30f;
#pragma unroll
        for (int l = 0; l < 6; l++) {
            v[l] = (g_lp[b * 36 + q * 6 + l] - ms[l]) * iv[l] * g1[l] + b1[l];
            mx = fmaxf(mx, v[l]);
        }
        float s = 0.f;
#pragma unroll
        for (int l = 0; l < 6; l++) { v[l] = expf(v[l] - mx); s += v[l]; }
        float inv = 1.f / s;
#pragma unroll
        for (int l = 0; l < 6; l++) g_Tc[b * 36 + l * 6 + q] = v[l] * inv;
    }
}

__global__ void k_xo(float* out) {
    __shared__ float ssum[256], ssq[256], tcs[36];
    int b = blockIdx.y, nc = blockIdx.x, tid = threadIdx.x;
    int c = tid >> 3, w = tid & 7;
    if (tid < 36) tcs[tid] = g_Tc[b * 36 + tid];
    __syncthreads();
    float s1 = 0.f, s2 = 0.f;
    for (int j = 0; j < 24; j++) {
        int e = w * 24 + j, n_l = e / 6, q = e - n_l * 6, n = nc * 32 + n_l;
        if (n >= 500) continue;
        int gi = ((b * 32 + c) * NN + n) * 6;
        float a = 0.f;
#pragma unroll
        for (int l = 0; l < 6; l++) a += g_g6[gi + l] * tcs[l * 6 + q];
        a = (a > 0.f) ? a : 0.01f * a;
        a += g_resid[(b * 32 + c) * NPOS + n * 10 + 4 + q];
        out[gi + q] = a;
        s1 += a; s2 += a * a;
    }
    ssum[tid] = s1; ssq[tid] = s2;
    __syncthreads();
    if (w == 0) {
        float a = 0.f, aa = 0.f;
        for (int k = 0; k < 8; k++) { a += ssum[c * 8 + k]; aa += ssq[c * 8 + k]; }
        int blk = b * 16 + nc;
        g_part[blk * 32 + c] = a;
        g_part[8192 + blk * 32 + c] = aa;
    }
}

__global__ void k_bn2stats(const float* g2, const float* b2) {
    int c = threadIdx.x;
    if (c >= 32) return;
    float s = 0.f, s2 = 0.f;
    for (int i = 0; i < 256; i++) { s += g_part[i * 32 + c]; s2 += g_part[8192 + i * 32 + c]; }
    float mu = s / 48000.f, var = s2 / 48000.f - mu * mu;
    float scale = g2[c] * rsqrtf(var + 1e-5f);
    g_stats[c] = scale;
    g_stats[32 + c] = b2[c] - mu * scale;
}

__global__ void k_bn2apply(float* out) {
    int i = blockIdx.x * 256 + threadIdx.x;
    if (i >= 1536000) return;
    int c = (i / 3000) & 31;
    out[i] = out[i] * g_stats[c] + g_stats[32 + c];
}

extern "C" void kernel_launch(void* const* d_in, const int* in_sizes, int n_in,
                              void* d_out, int out_size) {
    const float *x = (const float*)d_in[0], *A = (const float*)d_in[1];
    const float *c1W = (const float*)d_in[2], *c1b = (const float*)d_in[3];
    const float *t1W = (const float*)d_in[4], *t1b = (const float*)d_in[5];
    const float *qW = (const float*)d_in[6], *qb = (const float*)d_in[7];
    const float *kW = (const float*)d_in[8], *kb = (const float*)d_in[9];
    const float *vW = (const float*)d_in[10], *vb = (const float*)d_in[11];
    const float *oW = (const float*)d_in[12], *ob = (const float*)d_in[13];
    const float *t2W = (const float*)d_in[14], *t2b = (const float*)d_in[15];
    const float *mW = (const float*)d_in[16], *mb = (const float*)d_in[17];
    const float *ctW = (const float*)d_in[18], *ctb = (const float*)d_in[19];
    const float *tc1 = (const float*)d_in[20], *tc2 = (const float*)d_in[21];
    const float *tw = (const float*)d_in[22], *tb = (const float*)d_in[23];
    const float *tv = (const float*)d_in[24];
    const float *b1g = (const float*)d_in[25], *b1b = (const float*)d_in[26];
    const float *b2g = (const float*)d_in[27], *b2b = (const float*)d_in[28];
    float* out = (float*)d_out;

    static int configured = 0;
    if (!configured) {
        cudaFuncSetAttribute(k_qkv, cudaFuncAttributeMaxDynamicSharedMemorySize, 49152);
        cudaFuncSetAttribute(k_mlp, cudaFuncAttributeMaxDynamicSharedMemorySize, 63488);
        cudaFuncSetAttribute(k_attn, cudaFuncAttributeMaxDynamicSharedMemorySize, 49792);
        cudaFuncSetAttribute(k_gemm2, cudaFuncAttributeMaxDynamicSharedMemorySize, 23040);
        configured = 1;
    }

    k_wprep<<<70, 256>>>(qW, kW, vW, t1W, t1b, qb, kb, vb, t2W, oW, ob, t2b);
    k_conv1<<<dim3(16, 20), 256>>>(x, c1W, c1b);
    k_qkv<<<dim3(16, 79), 256, 49152>>>(x);
    k_attn<<<dim3(125, 16), 256, 49792>>>();
    k_scores<<<dim3(36, 160), dim3(16, 16)>>>();
    k_softmax<<<dim3(160, 63), 256>>>();
    k_gemm2<<<dim3(4, 160, 2), 256, 23040>>>(A, 0);
    k_gemm2<<<dim3(4, 160, 2), 256, 23040>>>(A, 1);
    k_mlp<<<dim3(16, 160), 256, 63488>>>(mW, mb);
    k_ct1<<<1000, 256>>>(ctW, ctb);
    k_tatt<<<16, 256>>>(tc1, tc2, tw, tb, tv);
    k_bn1<<<1, 128>>>(b1g, b1b);
    k_xo<<<dim3(16, 16), 256>>>(out);
    k_bn2stats<<<1, 32>>>(b2g, b2b);
    k_bn2apply<<<6000, 256>>>(out);
}